// round 12
// baseline (speedup 1.0000x reference)
#include <cuda_runtime.h>
#include <cuda_bf16.h>
#include <math.h>
#include <stdint.h>

#define B_   4
#define L_   4096
#define D_   1024
#define H_   16
#define DK_  64
#define BH_  (B_ * H_)
#define TOPK 8
#define M_   (B_ * L_)   // 16384
#define KW_  1536        // split-K words per row: [hi 512 | hi 512 | lo 512]
#define NKT  48          // KW_/32 mainloop iterations

// ---------------- scratch (device globals; no runtime allocation) ----------
__device__ float g_Vp[M_ * D_];
__device__ uint32_t g_Avw[M_ * KW_];      // split-bf16 words of values
__device__ uint32_t g_Prew[M_ * KW_];     // split-bf16 words of gathered pre
__device__ uint32_t g_Bvw[KW_ * D_];      // split-bf16 words of Wv (kk-major, n-permuted)
__device__ uint32_t g_Bow[KW_ * D_];      // same for Wo
__device__ float g_qm[BH_ * L_];
__device__ float g_km[BH_ * L_];
__device__ float g_Wm[2 * H_ * D_];
__device__ float g_w[BH_ * TOPK];
__device__ int   g_delays[BH_ * TOPK];

// ---------------- helpers ----------------------------------------------------
__device__ __forceinline__ uint32_t smem_u32(const void* p) {
    uint32_t a;
    asm("{ .reg .u64 t; cvta.to.shared.u64 t, %1; cvt.u32.u64 %0, t; }"
        : "=r"(a) : "l"(p));
    return a;
}
__device__ __forceinline__ void cp16(uint32_t dst, const void* src) {
    asm volatile("cp.async.cg.shared.global [%0], [%1], 16;"
                 :: "r"(dst), "l"(src));
}
__device__ __forceinline__ uint32_t pack_bf16(float x, float y) {
    __nv_bfloat162 h = __floats2bfloat162_rn(x, y);
    return *(uint32_t*)&h;
}
__device__ __forceinline__ void mma_bf16(float* d, const uint32_t* a, const uint32_t* b) {
    asm volatile(
        "mma.sync.aligned.m16n8k16.row.col.f32.bf16.bf16.f32 "
        "{%0,%1,%2,%3}, {%4,%5,%6,%7}, {%8,%9}, {%0,%1,%2,%3};"
        : "+f"(d[0]), "+f"(d[1]), "+f"(d[2]), "+f"(d[3])
        : "r"(a[0]), "r"(a[1]), "r"(a[2]), "r"(a[3]), "r"(b[0]), "r"(b[1]));
}

// ---------------- convA: fp32 [M,1024] -> split-bf16 words [M,1536] ----------
__global__ __launch_bounds__(256) void convA_kernel(
    const float4* __restrict__ X, uint32_t* __restrict__ Aw)
{
    int gid = blockIdx.x * 256 + threadIdx.x;   // one float4 (4 k) each
    int m  = gid >> 8;
    int k4 = gid & 255;
    float4 x = X[gid];
    float hx0 = __bfloat162float(__float2bfloat16(x.x));
    float hx1 = __bfloat162float(__float2bfloat16(x.y));
    float hx2 = __bfloat162float(__float2bfloat16(x.z));
    float hx3 = __bfloat162float(__float2bfloat16(x.w));
    uint2 hi = make_uint2(pack_bf16(x.x, x.y), pack_bf16(x.z, x.w));
    uint2 lo = make_uint2(pack_bf16(x.x - hx0, x.y - hx1),
                          pack_bf16(x.z - hx2, x.w - hx3));
    uint32_t* row = Aw + (size_t)m * KW_ + k4 * 2;
    *(uint2*)(row)        = hi;   // hi block 1
    *(uint2*)(row + 512)  = hi;   // hi block 2
    *(uint2*)(row + 1024) = lo;   // lo block
}

// ---------------- wprep: W fp32 [k][n] -> split words [kk][n] (n permuted) --
// kk 0..511: hi(k=2kk,2kk+1); 512..1023: lo; 1024..1535: hi
__global__ __launch_bounds__(256) void wprep_bf16_kernel(
    const float* __restrict__ W, uint32_t* __restrict__ Bw)
{
    int id = blockIdx.x * 256 + threadIdx.x;    // 0 .. 1536*1024-1
    int kk = id >> 10;
    int p  = id & 1023;
    int g = p & ~63, pp = p & 63;
    int n = g + (((pp & 7) << 3) + (pp >> 3));
    int sec = kk >> 9;                // 0,1,2
    int kb  = (kk & 511) * 2;
    float f0 = __ldg(&W[(size_t)kb * 1024 + n]);
    float f1 = __ldg(&W[(size_t)(kb + 1) * 1024 + n]);
    uint32_t wv;
    if (sec == 1) {
        float h0 = __bfloat162float(__float2bfloat16(f0));
        float h1 = __bfloat162float(__float2bfloat16(f1));
        wv = pack_bf16(f0 - h0, f1 - h1);
    } else {
        wv = pack_bf16(f0, f1);
    }
    Bw[id] = wv;
}

// ---------------- split-bf16 mma GEMM: block 128x128, warp 32x64, occ 2 -----
#define A_ST_W 4096              // 128 rows x 32 words
#define STAGE_W 8192
#define STAGE_BYTES (STAGE_W * 4)
#define GEMM_SMEM (3 * STAGE_BYTES)   // 96 KB

__global__ __launch_bounds__(256, 2) void gemm_bf16_kernel(
    const uint32_t* __restrict__ Aw, const uint32_t* __restrict__ Bw,
    const float* __restrict__ bias, float* __restrict__ C)
{
    extern __shared__ uint32_t sm[];
    const uint32_t su = smem_u32(sm);
    const int tid = threadIdx.x;
    const int bn = blockIdx.x;           // 0..7
    const int bm = blockIdx.y;           // 0..127
    const int wid = tid >> 5, lane = tid & 31;
    const int wm = wid >> 1, wn = wid & 1;
    const int qr = lane >> 2, qc = lane & 3;

    const uint32_t* Ab = Aw + (size_t)(bm * 128 + (tid >> 3)) * KW_ + (tid & 7) * 4;
    const uint32_t* Wb = Bw + (size_t)(tid >> 5) * 1024 + bn * 128 + (tid & 31) * 4;

    uint32_t saoff[4], sboff[4];
    #pragma unroll
    for (int p = 0; p < 4; p++) {
        int row = (tid >> 3) + p * 32;
        saoff[p] = (row * 32 + (((tid & 7) ^ (row & 7)) << 2)) * 4;
        int k = (tid >> 5) + p * 8;
        sboff[p] = (A_ST_W + k * 128 + (((tid & 31) << 2) ^ ((k & 3) << 3))) * 4;
    }

    float acc[2][8][4];
    #pragma unroll
    for (int mb = 0; mb < 2; mb++)
        #pragma unroll
        for (int j = 0; j < 8; j++)
            #pragma unroll
            for (int v = 0; v < 4; v++) acc[mb][j][v] = 0.0f;

    auto load_stage = [&](int st, int kt) {
        uint32_t base = su + st * STAGE_BYTES;
        #pragma unroll
        for (int p = 0; p < 4; p++) {
            cp16(base + saoff[p], Ab + kt * 32 + p * 32 * KW_);
            cp16(base + sboff[p], Wb + (size_t)(kt * 32 + p * 8) * 1024);
        }
    };

    load_stage(0, 0);
    asm volatile("cp.async.commit_group;");
    load_stage(1, 1);
    asm volatile("cp.async.commit_group;");

    const int rowa0 = wm * 32 + qr;
    const int colb = (wn * 64 + qr * 8) ^ (qc << 3);

    for (int kt = 0; kt < NKT; kt++) {
        const int st = kt % 3;
        if (kt < NKT - 2) asm volatile("cp.async.wait_group 1;");
        else              asm volatile("cp.async.wait_group 0;");
        __syncthreads();
        if (kt < NKT - 2) {
            load_stage((kt + 2) % 3, kt + 2);
            asm volatile("cp.async.commit_group;");
        }

        const uint32_t* As = sm + st * STAGE_W;
        const uint32_t* Bs = As + A_ST_W;

        #pragma unroll
        for (int s = 0; s < 4; s++) {
            uint32_t afr[2][4];
            #pragma unroll
            for (int mb = 0; mb < 2; mb++) {
                int row = rowa0 + mb * 16;
                int s0 = (((s * 2)     ^ qr) << 2) + qc;
                int s1 = (((s * 2 + 1) ^ qr) << 2) + qc;
                afr[mb][0] = As[row * 32 + s0];
                afr[mb][1] = As[(row + 8) * 32 + s0];
                afr[mb][2] = As[row * 32 + s1];
                afr[mb][3] = As[(row + 8) * 32 + s1];
            }
            const uint4* br0 = (const uint4*)&Bs[(s * 8 + qc) * 128 + colb];
            const uint4* br1 = (const uint4*)&Bs[(s * 8 + qc + 4) * 128 + colb];
            uint4 b00 = br0[0], b01 = br0[1];
            uint4 b10 = br1[0], b11 = br1[1];
            uint32_t bfr[8][2];
            bfr[0][0] = b00.x; bfr[0][1] = b10.x;
            bfr[1][0] = b00.y; bfr[1][1] = b10.y;
            bfr[2][0] = b00.z; bfr[2][1] = b10.z;
            bfr[3][0] = b00.w; bfr[3][1] = b10.w;
            bfr[4][0] = b01.x; bfr[4][1] = b11.x;
            bfr[5][0] = b01.y; bfr[5][1] = b11.y;
            bfr[6][0] = b01.z; bfr[6][1] = b11.z;
            bfr[7][0] = b01.w; bfr[7][1] = b11.w;

            #pragma unroll
            for (int mb = 0; mb < 2; mb++)
                #pragma unroll
                for (int j = 0; j < 8; j++)
                    mma_bf16(acc[mb][j], afr[mb], bfr[j]);
        }
    }

    #pragma unroll
    for (int mb = 0; mb < 2; mb++) {
        int row = bm * 128 + wm * 32 + mb * 16 + qr;
        #pragma unroll
        for (int j = 0; j < 8; j++) {
            int col = bn * 128 + wn * 64 + j * 8 + qc * 2;
            float2 bb = *(const float2*)(bias + col);
            float2 o0 = make_float2(acc[mb][j][0] + bb.x, acc[mb][j][1] + bb.y);
            float2 o1 = make_float2(acc[mb][j][2] + bb.x, acc[mb][j][3] + bb.y);
            *(float2*)(C + (size_t)row * 1024 + col)       = o0;
            *(float2*)(C + (size_t)(row + 8) * 1024 + col) = o1;
        }
    }
}

// ---------------- mean-reduced weights --------------------------------------
__global__ __launch_bounds__(256) void wmean_kernel(
    const float* __restrict__ Wq, const float* __restrict__ Wk,
    float* __restrict__ Wm)
{
    int id = blockIdx.x * 256 + threadIdx.x;
    int t = id >> 14;
    int h = (id >> 10) & 15;
    int d = id & 1023;
    const float* W = t ? Wk : Wq;
    const float4* p = (const float4*)(W + (size_t)d * 1024 + h * 64);
    float s = 0.0f;
    #pragma unroll
    for (int c = 0; c < 16; c++) {
        float4 v = __ldg(&p[c]);
        s += (v.x + v.y) + (v.z + v.w);
    }
    Wm[id] = s * (1.0f / 64.0f);
}

// ---------------- skinny mean-projection ------------------------------------
__global__ __launch_bounds__(256) void qkmean_kernel(
    const float* __restrict__ queries, const float* __restrict__ keys,
    const float* __restrict__ Wm, float* __restrict__ qm, float* __restrict__ km)
{
    extern __shared__ float swm[];
    const int tid = threadIdx.x;
    for (int i = tid * 4; i < 32768; i += 1024)
        *(float4*)(swm + i) = *(const float4*)(Wm + i);
    __syncthreads();

    const int w = tid >> 5, lane = tid & 31;
    const int m0 = blockIdx.x * 32 + w * 4;

    #pragma unroll
    for (int ph = 0; ph < 2; ph++) {
        const float* src = ph ? keys : queries;
        float* dst = ph ? g_km : g_qm;
        const float* base = src + (size_t)m0 * 1024 + lane * 4;
        const float* tw_ = swm + ph * 16384 + lane * 4;

        float acc[4][16];
        #pragma unroll
        for (int r = 0; r < 4; r++)
            #pragma unroll
            for (int h = 0; h < 16; h++) acc[r][h] = 0.0f;

        #pragma unroll
        for (int c = 0; c < 8; c++) {
            float4 x0 = *(const float4*)(base + 0 * 1024 + c * 128);
            float4 x1 = *(const float4*)(base + 1 * 1024 + c * 128);
            float4 x2 = *(const float4*)(base + 2 * 1024 + c * 128);
            float4 x3 = *(const float4*)(base + 3 * 1024 + c * 128);
            #pragma unroll
            for (int h = 0; h < 16; h++) {
                float4 wv = *(const float4*)(tw_ + h * 1024 + c * 128);
                acc[0][h] += x0.x*wv.x + x0.y*wv.y + x0.z*wv.z + x0.w*wv.w;
                acc[1][h] += x1.x*wv.x + x1.y*wv.y + x1.z*wv.z + x1.w*wv.w;
                acc[2][h] += x2.x*wv.x + x2.y*wv.y + x2.z*wv.z + x2.w*wv.w;
                acc[3][h] += x3.x*wv.x + x3.y*wv.y + x3.z*wv.z + x3.w*wv.w;
            }
        }

        #pragma unroll
        for (int r = 0; r < 4; r++) {
            int m = m0 + r;
            int b = m >> 12, l = m & 4095;
            float* out = dst + (((size_t)b * 16) << 12) + l;
            #pragma unroll
            for (int h = 0; h < 16; h++) {
                float v = acc[r][h];
                v += __shfl_xor_sync(0xFFFFFFFFu, v, 16);
                v += __shfl_xor_sync(0xFFFFFFFFu, v, 8);
                v += __shfl_xor_sync(0xFFFFFFFFu, v, 4);
                v += __shfl_xor_sync(0xFFFFFFFFu, v, 2);
                v += __shfl_xor_sync(0xFFFFFFFFu, v, 1);
                if (lane == h) out[(size_t)h << 12] = v;
            }
        }
    }
}

// ---------------- FFT correlation + top-8 + softmax (fused, 512 thr) --------
__global__ __launch_bounds__(512) void fft_corr_top8_kernel(
    const float* __restrict__ qm, const float* __restrict__ km,
    float* __restrict__ w, int* __restrict__ delays)
{
    extern __shared__ float2 fsm[];
    float2* buf0 = fsm;
    float2* buf1 = fsm + 4096;
    float2* tw   = fsm + 8192;
    float*  sc   = (float*)(fsm + 8192);
    __shared__ float svals[512];
    __shared__ int   sidx[512];
    __shared__ float topv[TOPK];
    __shared__ int   topi[TOPK];

    const int bh = blockIdx.x, tid = threadIdx.x;
    const float* q = qm + (size_t)bh * L_;
    const float* k = km + (size_t)bh * L_;
    for (int i = tid; i < 4096; i += 512) buf0[i] = make_float2(q[i], k[i]);
    for (int r = tid; r < 2048; r += 512) {
        float sv, cv;
        __sincosf(-6.2831853071795865f * (float)r / 4096.0f, &sv, &cv);
        tw[r] = make_float2(cv, sv);
    }
    __syncthreads();

    // FFT #1
    {
        float2 *x = buf0, *y = buf1;
        for (int t = 0; t < 12; t++) {
            int s = 1 << t;
            #pragma unroll
            for (int ii = 0; ii < 4; ii++) {
                int idx = tid + ii * 512;
                float2 a = x[idx];
                float2 b = x[idx + 2048];
                int r = idx & ~(s - 1);
                int kl = idx & (s - 1);
                float2 wv = tw[r];
                float dx = a.x - b.x, dy = a.y - b.y;
                y[2 * r + kl]     = make_float2(a.x + b.x, a.y + b.y);
                y[2 * r + kl + s] = make_float2(dx * wv.x - dy * wv.y,
                                                dx * wv.y + dy * wv.x);
            }
            __syncthreads();
            float2* t2 = x; x = y; y = t2;
        }
    }

    // Hermitian split + conj(Q*conj(K)) into buf1
    for (int i = tid; i < 4096; i += 512) {
        float2 zi = buf0[i];
        float2 zn = buf0[(4096 - i) & 4095];
        float qx = 0.5f * (zi.x + zn.x);
        float qy = 0.5f * (zi.y - zn.y);
        float ux = zi.x - zn.x;
        float uy = zi.y + zn.y;
        float kx = 0.5f * uy;
        float ky = -0.5f * ux;
        float px = qx * kx + qy * ky;
        float py = qy * kx - qx * ky;
        buf1[i] = make_float2(px, -py);
    }
    __syncthreads();

    // FFT #2
    {
        float2 *x = buf1, *y = buf0;
        for (int t = 0; t < 12; t++) {
            int s = 1 << t;
            #pragma unroll
            for (int ii = 0; ii < 4; ii++) {
                int idx = tid + ii * 512;
                float2 a = x[idx];
                float2 b = x[idx + 2048];
                int r = idx & ~(s - 1);
                int kl = idx & (s - 1);
                float2 wv = tw[r];
                float dx = a.x - b.x, dy = a.y - b.y;
                y[2 * r + kl]     = make_float2(a.x + b.x, a.y + b.y);
                y[2 * r + kl + s] = make_float2(dx * wv.x - dy * wv.y,
                                                dx * wv.y + dy * wv.x);
            }
            __syncthreads();
            float2* t2 = x; x = y; y = t2;
        }
    }

    for (int i = tid; i < 4096; i += 512)
        sc[i] = buf1[i].x * (1.0f / 4096.0f);
    __syncthreads();

    for (int r = 0; r < TOPK; r++) {
        float best = -INFINITY; int bi = 0;
        for (int i = tid; i < 4096; i += 512) {
            float v = sc[i];
            if (v > best) { best = v; bi = i; }
        }
        svals[tid] = best;
        sidx[tid] = bi;
        __syncthreads();
        for (int s = 256; s > 0; s >>= 1) {
            if (tid < s) {
                float v2 = svals[tid + s];
                int   i2 = sidx[tid + s];
                float v1 = svals[tid];
                int   i1 = sidx[tid];
                if (v2 > v1 || (v2 == v1 && i2 < i1)) {
                    svals[tid] = v2;
                    sidx[tid] = i2;
                }
            }
            __syncthreads();
        }
        if (tid == 0) {
            topv[r] = svals[0];
            topi[r] = sidx[0];
            sc[sidx[0]] = -INFINITY;
        }
        __syncthreads();
    }

    if (tid == 0) {
        float mx = topv[0];
        float e[TOPK], s = 0.0f;
        #pragma unroll
        for (int r = 0; r < TOPK; r++) { e[r] = expf(topv[r] - mx); s += e[r]; }
        float inv = 1.0f / s;
        #pragma unroll
        for (int r = 0; r < TOPK; r++) {
            w[bh * TOPK + r] = e[r] * inv;
            delays[bh * TOPK + r] = topi[r];
        }
    }
}

// ---------------- gather: weighted roll -> split-bf16 words directly ---------
__global__ __launch_bounds__(256) void gather_kernel(
    const float* __restrict__ Vp, const float* __restrict__ w,
    const int* __restrict__ delays, uint32_t* __restrict__ Prew)
{
    unsigned gid = blockIdx.x * blockDim.x + threadIdx.x;   // one float4 each
    int d4 = gid & 255;
    int l  = (gid >> 8) & (L_ - 1);
    int b  = gid >> 20;
    int h  = d4 >> 4;
    int bh = b * H_ + h;

    float4 a = make_float4(0.f, 0.f, 0.f, 0.f);
    #pragma unroll
    for (int r = 0; r < TOPK; r++) {
        float wr = __ldg(&w[bh * TOPK + r]);
        int   dl = __ldg(&delays[bh * TOPK + r]);
        int   lm = (l - dl) & (L_ - 1);
        const float4 v = *(const float4*)(Vp + (size_t)(b * L_ + lm) * D_ + d4 * 4);
        a.x += wr * v.x; a.y += wr * v.y; a.z += wr * v.z; a.w += wr * v.w;
    }

    float hx0 = __bfloat162float(__float2bfloat16(a.x));
    float hx1 = __bfloat162float(__float2bfloat16(a.y));
    float hx2 = __bfloat162float(__float2bfloat16(a.z));
    float hx3 = __bfloat162float(__float2bfloat16(a.w));
    uint2 hi = make_uint2(pack_bf16(a.x, a.y), pack_bf16(a.z, a.w));
    uint2 lo = make_uint2(pack_bf16(a.x - hx0, a.y - hx1),
                          pack_bf16(a.z - hx2, a.w - hx3));
    int m = b * L_ + l;
    uint32_t* row = Prew + (size_t)m * KW_ + d4 * 2;
    *(uint2*)(row)        = hi;
    *(uint2*)(row + 512)  = hi;
    *(uint2*)(row + 1024) = lo;
}

// ---------------- launch ------------------------------------------------------
extern "C" void kernel_launch(void* const* d_in, const int* in_sizes, int n_in,
                              void* d_out, int out_size)
{
    const float* queries = (const float*)d_in[0];
    const float* keys    = (const float*)d_in[1];
    const float* values  = (const float*)d_in[2];
    const float* Wq = (const float*)d_in[3];
    const float* Wk = (const float*)d_in[5];
    const float* Wv = (const float*)d_in[7];
    const float* bv = (const float*)d_in[8];
    const float* Wo = (const float*)d_in[9];
    const float* bo = (const float*)d_in[10];
    float* out = (float*)d_out;

    float *Vp, *qm, *km, *Wm, *w;
    uint32_t *Avw, *Prew, *Bvw, *Bow;
    int* delays;
    cudaGetSymbolAddress((void**)&Vp, g_Vp);
    cudaGetSymbolAddress((void**)&Avw, g_Avw);
    cudaGetSymbolAddress((void**)&Prew, g_Prew);
    cudaGetSymbolAddress((void**)&Bvw, g_Bvw);
    cudaGetSymbolAddress((void**)&Bow, g_Bow);
    cudaGetSymbolAddress((void**)&qm, g_qm);
    cudaGetSymbolAddress((void**)&km, g_km);
    cudaGetSymbolAddress((void**)&Wm, g_Wm);
    cudaGetSymbolAddress((void**)&w, g_w);
    cudaGetSymbolAddress((void**)&delays, g_delays);

    cudaFuncSetAttribute(gemm_bf16_kernel,
                         cudaFuncAttributeMaxDynamicSharedMemorySize, GEMM_SMEM);
    cudaFuncSetAttribute(qkmean_kernel,
                         cudaFuncAttributeMaxDynamicSharedMemorySize, 131072);
    cudaFuncSetAttribute(fft_corr_top8_kernel,
                         cudaFuncAttributeMaxDynamicSharedMemorySize, 81920);

    dim3 gemm_grid(8, 128);

    // fork-join: side chain depends only on inputs
    cudaStream_t side;
    cudaEvent_t evFork, evJoin;
    cudaStreamCreateWithFlags(&side, cudaStreamNonBlocking);
    cudaEventCreateWithFlags(&evFork, cudaEventDisableTiming);
    cudaEventCreateWithFlags(&evJoin, cudaEventDisableTiming);

    cudaEventRecord(evFork, 0);
    cudaStreamWaitEvent(side, evFork, 0);

    // main stream: V projection (critical path)
    wprep_bf16_kernel<<<6144, 256>>>(Wv, Bvw);
    convA_kernel<<<M_, 256>>>((const float4*)values, Avw);
    gemm_bf16_kernel<<<gemm_grid, 256, GEMM_SMEM>>>(Avw, Bvw, bv, Vp);

    // side stream: mean path + Wo prep (hidden under V-GEMM)
    wprep_bf16_kernel<<<6144, 256, 0, side>>>(Wo, Bow);
    wmean_kernel<<<128, 256, 0, side>>>(Wq, Wk, Wm);
    qkmean_kernel<<<512, 256, 131072, side>>>(queries, keys, Wm, qm, km);
    fft_corr_top8_kernel<<<BH_, 512, 81920, side>>>(qm, km, w, delays);
    cudaEventRecord(evJoin, side);

    // join, then gather + output projection
    cudaStreamWaitEvent(0, evJoin, 0);
    gather_kernel<<<(M_ * D_ / 4) / 256, 256>>>(Vp, w, delays, Prew);
    gemm_bf16_kernel<<<gemm_grid, 256, GEMM_SMEM>>>(Prew, Bow, bo, out);
}

// round 13
// speedup vs baseline: 1.9757x; 1.9757x over previous
#include <cuda_runtime.h>
#include <cuda_bf16.h>
#include <cuda_fp16.h>
#include <math.h>
#include <stdint.h>

#define B_   4
#define L_   4096
#define D_   1024
#define H_   16
#define DK_  64
#define BH_  (B_ * H_)
#define TOPK 8
#define M_   (B_ * L_)   // 16384
#define KW_  512         // fp16 k-pair words per row (K=1024)
#define NKT  16          // KW_/32 mainloop iterations

// ---------------- scratch (device globals; no runtime allocation) ----------
__device__ float g_Vp[M_ * D_];
__device__ uint32_t g_Avw[M_ * KW_];      // fp16-pair words of values
__device__ uint32_t g_Prew[M_ * KW_];     // fp16-pair words of gathered pre
__device__ uint32_t g_Bvw[KW_ * D_];      // fp16-pair words of Wv (kk-major, n-permuted)
__device__ uint32_t g_Bow[KW_ * D_];      // same for Wo
__device__ float g_qm[BH_ * L_];
__device__ float g_km[BH_ * L_];
__device__ float g_Wm[2 * H_ * D_];
__device__ float g_w[BH_ * TOPK];
__device__ int   g_delays[BH_ * TOPK];

// ---------------- helpers ----------------------------------------------------
__device__ __forceinline__ uint32_t smem_u32(const void* p) {
    uint32_t a;
    asm("{ .reg .u64 t; cvta.to.shared.u64 t, %1; cvt.u32.u64 %0, t; }"
        : "=r"(a) : "l"(p));
    return a;
}
__device__ __forceinline__ void cp16(uint32_t dst, const void* src) {
    asm volatile("cp.async.cg.shared.global [%0], [%1], 16;"
                 :: "r"(dst), "l"(src));
}
__device__ __forceinline__ uint32_t pack_f16(float x, float y) {
    __half2 h = __floats2half2_rn(x, y);
    return *(uint32_t*)&h;
}
__device__ __forceinline__ void mma_f16(float* d, const uint32_t* a, const uint32_t* b) {
    asm volatile(
        "mma.sync.aligned.m16n8k16.row.col.f32.f16.f16.f32 "
        "{%0,%1,%2,%3}, {%4,%5,%6,%7}, {%8,%9}, {%0,%1,%2,%3};"
        : "+f"(d[0]), "+f"(d[1]), "+f"(d[2]), "+f"(d[3])
        : "r"(a[0]), "r"(a[1]), "r"(a[2]), "r"(a[3]), "r"(b[0]), "r"(b[1]));
}

// ---------------- convA: fp32 [M,1024] -> fp16-pair words [M,512] ------------
__global__ __launch_bounds__(256) void convA_kernel(
    const float4* __restrict__ X, uint32_t* __restrict__ Aw)
{
    int gid = blockIdx.x * 256 + threadIdx.x;   // one float4 (4 k) each
    int m  = gid >> 8;
    int k4 = gid & 255;
    float4 x = X[gid];
    *(uint2*)(Aw + (size_t)m * KW_ + k4 * 2) =
        make_uint2(pack_f16(x.x, x.y), pack_f16(x.z, x.w));
}

// ---------------- wprep: W fp32 [k][n] -> fp16 words [kk][n] (n permuted) ---
__global__ __launch_bounds__(256) void wprep_f16_kernel(
    const float* __restrict__ W, uint32_t* __restrict__ Bw)
{
    int id = blockIdx.x * 256 + threadIdx.x;    // 0 .. 512*1024-1
    int kk = id >> 10;
    int p  = id & 1023;
    int g = p & ~63, pp = p & 63;
    int n = g + (((pp & 7) << 3) + (pp >> 3));
    int kb = kk * 2;
    float f0 = __ldg(&W[(size_t)kb * 1024 + n]);
    float f1 = __ldg(&W[(size_t)(kb + 1) * 1024 + n]);
    Bw[id] = pack_f16(f0, f1);
}

// ---------------- fp16 mma GEMM: block 128x128, warp 32x64, occ 2 -----------
#define A_ST_W 4096              // 128 rows x 32 words
#define STAGE_W 8192
#define STAGE_BYTES (STAGE_W * 4)
#define GEMM_SMEM (3 * STAGE_BYTES)   // 96 KB

__global__ __launch_bounds__(256, 2) void gemm_f16_kernel(
    const uint32_t* __restrict__ Aw, const uint32_t* __restrict__ Bw,
    const float* __restrict__ bias, float* __restrict__ C)
{
    extern __shared__ uint32_t sm[];
    const uint32_t su = smem_u32(sm);
    const int tid = threadIdx.x;
    const int bn = blockIdx.x;           // 0..7
    const int bm = blockIdx.y;           // 0..127
    const int wid = tid >> 5, lane = tid & 31;
    const int wm = wid >> 1, wn = wid & 1;
    const int qr = lane >> 2, qc = lane & 3;

    const uint32_t* Ab = Aw + (size_t)(bm * 128 + (tid >> 3)) * KW_ + (tid & 7) * 4;
    const uint32_t* Wb = Bw + (size_t)(tid >> 5) * 1024 + bn * 128 + (tid & 31) * 4;

    uint32_t saoff[4], sboff[4];
    #pragma unroll
    for (int p = 0; p < 4; p++) {
        int row = (tid >> 3) + p * 32;
        saoff[p] = (row * 32 + (((tid & 7) ^ (row & 7)) << 2)) * 4;
        int k = (tid >> 5) + p * 8;
        sboff[p] = (A_ST_W + k * 128 + (((tid & 31) << 2) ^ ((k & 3) << 3))) * 4;
    }

    float acc[2][8][4];
    #pragma unroll
    for (int mb = 0; mb < 2; mb++)
        #pragma unroll
        for (int j = 0; j < 8; j++)
            #pragma unroll
            for (int v = 0; v < 4; v++) acc[mb][j][v] = 0.0f;

    auto load_stage = [&](int st, int kt) {
        uint32_t base = su + st * STAGE_BYTES;
        #pragma unroll
        for (int p = 0; p < 4; p++) {
            cp16(base + saoff[p], Ab + kt * 32 + p * 32 * KW_);
            cp16(base + sboff[p], Wb + (size_t)(kt * 32 + p * 8) * 1024);
        }
    };

    load_stage(0, 0);
    asm volatile("cp.async.commit_group;");
    load_stage(1, 1);
    asm volatile("cp.async.commit_group;");

    const int rowa0 = wm * 32 + qr;
    const int colb = (wn * 64 + qr * 8) ^ (qc << 3);

    for (int kt = 0; kt < NKT; kt++) {
        const int st = kt % 3;
        if (kt < NKT - 2) asm volatile("cp.async.wait_group 1;");
        else              asm volatile("cp.async.wait_group 0;");
        __syncthreads();
        if (kt < NKT - 2) {
            load_stage((kt + 2) % 3, kt + 2);
            asm volatile("cp.async.commit_group;");
        }

        const uint32_t* As = sm + st * STAGE_W;
        const uint32_t* Bs = As + A_ST_W;

        #pragma unroll
        for (int s = 0; s < 4; s++) {
            uint32_t afr[2][4];
            #pragma unroll
            for (int mb = 0; mb < 2; mb++) {
                int row = rowa0 + mb * 16;
                int s0 = (((s * 2)     ^ qr) << 2) + qc;
                int s1 = (((s * 2 + 1) ^ qr) << 2) + qc;
                afr[mb][0] = As[row * 32 + s0];
                afr[mb][1] = As[(row + 8) * 32 + s0];
                afr[mb][2] = As[row * 32 + s1];
                afr[mb][3] = As[(row + 8) * 32 + s1];
            }
            const uint4* br0 = (const uint4*)&Bs[(s * 8 + qc) * 128 + colb];
            const uint4* br1 = (const uint4*)&Bs[(s * 8 + qc + 4) * 128 + colb];
            uint4 b00 = br0[0], b01 = br0[1];
            uint4 b10 = br1[0], b11 = br1[1];
            uint32_t bfr[8][2];
            bfr[0][0] = b00.x; bfr[0][1] = b10.x;
            bfr[1][0] = b00.y; bfr[1][1] = b10.y;
            bfr[2][0] = b00.z; bfr[2][1] = b10.z;
            bfr[3][0] = b00.w; bfr[3][1] = b10.w;
            bfr[4][0] = b01.x; bfr[4][1] = b11.x;
            bfr[5][0] = b01.y; bfr[5][1] = b11.y;
            bfr[6][0] = b01.z; bfr[6][1] = b11.z;
            bfr[7][0] = b01.w; bfr[7][1] = b11.w;

            #pragma unroll
            for (int mb = 0; mb < 2; mb++)
                #pragma unroll
                for (int j = 0; j < 8; j++)
                    mma_f16(acc[mb][j], afr[mb], bfr[j]);
        }
    }

    #pragma unroll
    for (int mb = 0; mb < 2; mb++) {
        int row = bm * 128 + wm * 32 + mb * 16 + qr;
        #pragma unroll
        for (int j = 0; j < 8; j++) {
            int col = bn * 128 + wn * 64 + j * 8 + qc * 2;
            float2 bb = *(const float2*)(bias + col);
            float2 o0 = make_float2(acc[mb][j][0] + bb.x, acc[mb][j][1] + bb.y);
            float2 o1 = make_float2(acc[mb][j][2] + bb.x, acc[mb][j][3] + bb.y);
            *(float2*)(C + (size_t)row * 1024 + col)       = o0;
            *(float2*)(C + (size_t)(row + 8) * 1024 + col) = o1;
        }
    }
}

// ---------------- mean-reduced weights --------------------------------------
__global__ __launch_bounds__(256) void wmean_kernel(
    const float* __restrict__ Wq, const float* __restrict__ Wk,
    float* __restrict__ Wm)
{
    int id = blockIdx.x * 256 + threadIdx.x;
    int t = id >> 14;
    int h = (id >> 10) & 15;
    int d = id & 1023;
    const float* W = t ? Wk : Wq;
    const float4* p = (const float4*)(W + (size_t)d * 1024 + h * 64);
    float s = 0.0f;
    #pragma unroll
    for (int c = 0; c < 16; c++) {
        float4 v = __ldg(&p[c]);
        s += (v.x + v.y) + (v.z + v.w);
    }
    Wm[id] = s * (1.0f / 64.0f);
}

// ---------------- skinny mean-projection ------------------------------------
__global__ __launch_bounds__(256) void qkmean_kernel(
    const float* __restrict__ queries, const float* __restrict__ keys,
    const float* __restrict__ Wm, float* __restrict__ qm, float* __restrict__ km)
{
    extern __shared__ float swm[];
    const int tid = threadIdx.x;
    for (int i = tid * 4; i < 32768; i += 1024)
        *(float4*)(swm + i) = *(const float4*)(Wm + i);
    __syncthreads();

    const int w = tid >> 5, lane = tid & 31;
    const int m0 = blockIdx.x * 32 + w * 4;

    #pragma unroll
    for (int ph = 0; ph < 2; ph++) {
        const float* src = ph ? keys : queries;
        float* dst = ph ? g_km : g_qm;
        const float* base = src + (size_t)m0 * 1024 + lane * 4;
        const float* tw_ = swm + ph * 16384 + lane * 4;

        float acc[4][16];
        #pragma unroll
        for (int r = 0; r < 4; r++)
            #pragma unroll
            for (int h = 0; h < 16; h++) acc[r][h] = 0.0f;

        #pragma unroll
        for (int c = 0; c < 8; c++) {
            float4 x0 = *(const float4*)(base + 0 * 1024 + c * 128);
            float4 x1 = *(const float4*)(base + 1 * 1024 + c * 128);
            float4 x2 = *(const float4*)(base + 2 * 1024 + c * 128);
            float4 x3 = *(const float4*)(base + 3 * 1024 + c * 128);
            #pragma unroll
            for (int h = 0; h < 16; h++) {
                float4 wv = *(const float4*)(tw_ + h * 1024 + c * 128);
                acc[0][h] += x0.x*wv.x + x0.y*wv.y + x0.z*wv.z + x0.w*wv.w;
                acc[1][h] += x1.x*wv.x + x1.y*wv.y + x1.z*wv.z + x1.w*wv.w;
                acc[2][h] += x2.x*wv.x + x2.y*wv.y + x2.z*wv.z + x2.w*wv.w;
                acc[3][h] += x3.x*wv.x + x3.y*wv.y + x3.z*wv.z + x3.w*wv.w;
            }
        }

        #pragma unroll
        for (int r = 0; r < 4; r++) {
            int m = m0 + r;
            int b = m >> 12, l = m & 4095;
            float* out = dst + (((size_t)b * 16) << 12) + l;
            #pragma unroll
            for (int h = 0; h < 16; h++) {
                float v = acc[r][h];
                v += __shfl_xor_sync(0xFFFFFFFFu, v, 16);
                v += __shfl_xor_sync(0xFFFFFFFFu, v, 8);
                v += __shfl_xor_sync(0xFFFFFFFFu, v, 4);
                v += __shfl_xor_sync(0xFFFFFFFFu, v, 2);
                v += __shfl_xor_sync(0xFFFFFFFFu, v, 1);
                if (lane == h) out[(size_t)h << 12] = v;
            }
        }
    }
}

// ---------------- FFT correlation + top-8 + softmax (fused, 512 thr) --------
__global__ __launch_bounds__(512) void fft_corr_top8_kernel(
    const float* __restrict__ qm, const float* __restrict__ km,
    float* __restrict__ w, int* __restrict__ delays)
{
    extern __shared__ float2 fsm[];
    float2* buf0 = fsm;
    float2* buf1 = fsm + 4096;
    float2* tw   = fsm + 8192;
    float*  sc   = (float*)(fsm + 8192);
    __shared__ float svals[512];
    __shared__ int   sidx[512];
    __shared__ float topv[TOPK];
    __shared__ int   topi[TOPK];

    const int bh = blockIdx.x, tid = threadIdx.x;
    const float* q = qm + (size_t)bh * L_;
    const float* k = km + (size_t)bh * L_;
    for (int i = tid; i < 4096; i += 512) buf0[i] = make_float2(q[i], k[i]);
    for (int r = tid; r < 2048; r += 512) {
        float sv, cv;
        __sincosf(-6.2831853071795865f * (float)r / 4096.0f, &sv, &cv);
        tw[r] = make_float2(cv, sv);
    }
    __syncthreads();

    // FFT #1
    {
        float2 *x = buf0, *y = buf1;
        for (int t = 0; t < 12; t++) {
            int s = 1 << t;
            #pragma unroll
            for (int ii = 0; ii < 4; ii++) {
                int idx = tid + ii * 512;
                float2 a = x[idx];
                float2 b = x[idx + 2048];
                int r = idx & ~(s - 1);
                int kl = idx & (s - 1);
                float2 wv = tw[r];
                float dx = a.x - b.x, dy = a.y - b.y;
                y[2 * r + kl]     = make_float2(a.x + b.x, a.y + b.y);
                y[2 * r + kl + s] = make_float2(dx * wv.x - dy * wv.y,
                                                dx * wv.y + dy * wv.x);
            }
            __syncthreads();
            float2* t2 = x; x = y; y = t2;
        }
    }

    // Hermitian split + conj(Q*conj(K)) into buf1
    for (int i = tid; i < 4096; i += 512) {
        float2 zi = buf0[i];
        float2 zn = buf0[(4096 - i) & 4095];
        float qx = 0.5f * (zi.x + zn.x);
        float qy = 0.5f * (zi.y - zn.y);
        float ux = zi.x - zn.x;
        float uy = zi.y + zn.y;
        float kx = 0.5f * uy;
        float ky = -0.5f * ux;
        float px = qx * kx + qy * ky;
        float py = qy * kx - qx * ky;
        buf1[i] = make_float2(px, -py);
    }
    __syncthreads();

    // FFT #2
    {
        float2 *x = buf1, *y = buf0;
        for (int t = 0; t < 12; t++) {
            int s = 1 << t;
            #pragma unroll
            for (int ii = 0; ii < 4; ii++) {
                int idx = tid + ii * 512;
                float2 a = x[idx];
                float2 b = x[idx + 2048];
                int r = idx & ~(s - 1);
                int kl = idx & (s - 1);
                float2 wv = tw[r];
                float dx = a.x - b.x, dy = a.y - b.y;
                y[2 * r + kl]     = make_float2(a.x + b.x, a.y + b.y);
                y[2 * r + kl + s] = make_float2(dx * wv.x - dy * wv.y,
                                                dx * wv.y + dy * wv.x);
            }
            __syncthreads();
            float2* t2 = x; x = y; y = t2;
        }
    }

    for (int i = tid; i < 4096; i += 512)
        sc[i] = buf1[i].x * (1.0f / 4096.0f);
    __syncthreads();

    for (int r = 0; r < TOPK; r++) {
        float best = -INFINITY; int bi = 0;
        for (int i = tid; i < 4096; i += 512) {
            float v = sc[i];
            if (v > best) { best = v; bi = i; }
        }
        svals[tid] = best;
        sidx[tid] = bi;
        __syncthreads();
        for (int s = 256; s > 0; s >>= 1) {
            if (tid < s) {
                float v2 = svals[tid + s];
                int   i2 = sidx[tid + s];
                float v1 = svals[tid];
                int   i1 = sidx[tid];
                if (v2 > v1 || (v2 == v1 && i2 < i1)) {
                    svals[tid] = v2;
                    sidx[tid] = i2;
                }
            }
            __syncthreads();
        }
        if (tid == 0) {
            topv[r] = svals[0];
            topi[r] = sidx[0];
            sc[sidx[0]] = -INFINITY;
        }
        __syncthreads();
    }

    if (tid == 0) {
        float mx = topv[0];
        float e[TOPK], s = 0.0f;
        #pragma unroll
        for (int r = 0; r < TOPK; r++) { e[r] = expf(topv[r] - mx); s += e[r]; }
        float inv = 1.0f / s;
        #pragma unroll
        for (int r = 0; r < TOPK; r++) {
            w[bh * TOPK + r] = e[r] * inv;
            delays[bh * TOPK + r] = topi[r];
        }
    }
}

// ---------------- gather: weighted roll -> fp16 words directly ---------------
__global__ __launch_bounds__(256) void gather_kernel(
    const float* __restrict__ Vp, const float* __restrict__ w,
    const int* __restrict__ delays, uint32_t* __restrict__ Prew)
{
    unsigned gid = blockIdx.x * blockDim.x + threadIdx.x;   // one float4 each
    int d4 = gid & 255;
    int l  = (gid >> 8) & (L_ - 1);
    int b  = gid >> 20;
    int h  = d4 >> 4;
    int bh = b * H_ + h;

    float4 a = make_float4(0.f, 0.f, 0.f, 0.f);
    #pragma unroll
    for (int r = 0; r < TOPK; r++) {
        float wr = __ldg(&w[bh * TOPK + r]);
        int   dl = __ldg(&delays[bh * TOPK + r]);
        int   lm = (l - dl) & (L_ - 1);
        const float4 v = *(const float4*)(Vp + (size_t)(b * L_ + lm) * D_ + d4 * 4);
        a.x += wr * v.x; a.y += wr * v.y; a.z += wr * v.z; a.w += wr * v.w;
    }
    int m = b * L_ + l;
    *(uint2*)(Prew + (size_t)m * KW_ + d4 * 2) =
        make_uint2(pack_f16(a.x, a.y), pack_f16(a.z, a.w));
}

// ---------------- launch ------------------------------------------------------
extern "C" void kernel_launch(void* const* d_in, const int* in_sizes, int n_in,
                              void* d_out, int out_size)
{
    const float* queries = (const float*)d_in[0];
    const float* keys    = (const float*)d_in[1];
    const float* values  = (const float*)d_in[2];
    const float* Wq = (const float*)d_in[3];
    const float* Wk = (const float*)d_in[5];
    const float* Wv = (const float*)d_in[7];
    const float* bv = (const float*)d_in[8];
    const float* Wo = (const float*)d_in[9];
    const float* bo = (const float*)d_in[10];
    float* out = (float*)d_out;

    float *Vp, *qm, *km, *Wm, *w;
    uint32_t *Avw, *Prew, *Bvw, *Bow;
    int* delays;
    cudaGetSymbolAddress((void**)&Vp, g_Vp);
    cudaGetSymbolAddress((void**)&Avw, g_Avw);
    cudaGetSymbolAddress((void**)&Prew, g_Prew);
    cudaGetSymbolAddress((void**)&Bvw, g_Bvw);
    cudaGetSymbolAddress((void**)&Bow, g_Bow);
    cudaGetSymbolAddress((void**)&qm, g_qm);
    cudaGetSymbolAddress((void**)&km, g_km);
    cudaGetSymbolAddress((void**)&Wm, g_Wm);
    cudaGetSymbolAddress((void**)&w, g_w);
    cudaGetSymbolAddress((void**)&delays, g_delays);

    cudaFuncSetAttribute(gemm_f16_kernel,
                         cudaFuncAttributeMaxDynamicSharedMemorySize, GEMM_SMEM);
    cudaFuncSetAttribute(qkmean_kernel,
                         cudaFuncAttributeMaxDynamicSharedMemorySize, 131072);
    cudaFuncSetAttribute(fft_corr_top8_kernel,
                         cudaFuncAttributeMaxDynamicSharedMemorySize, 81920);

    dim3 gemm_grid(8, 128);

    // fork-join: side chain depends only on inputs
    cudaStream_t side;
    cudaEvent_t evFork, evJoin;
    cudaStreamCreateWithFlags(&side, cudaStreamNonBlocking);
    cudaEventCreateWithFlags(&evFork, cudaEventDisableTiming);
    cudaEventCreateWithFlags(&evJoin, cudaEventDisableTiming);

    cudaEventRecord(evFork, 0);
    cudaStreamWaitEvent(side, evFork, 0);

    // main stream: V projection (critical path)
    wprep_f16_kernel<<<2048, 256>>>(Wv, Bvw);
    convA_kernel<<<M_, 256>>>((const float4*)values, Avw);
    gemm_f16_kernel<<<gemm_grid, 256, GEMM_SMEM>>>(Avw, Bvw, bv, Vp);

    // side stream: mean path + Wo prep (hidden under V-GEMM)
    wprep_f16_kernel<<<2048, 256, 0, side>>>(Wo, Bow);
    wmean_kernel<<<128, 256, 0, side>>>(Wq, Wk, Wm);
    qkmean_kernel<<<512, 256, 131072, side>>>(queries, keys, Wm, qm, km);
    fft_corr_top8_kernel<<<BH_, 512, 81920, side>>>(qm, km, w, delays);
    cudaEventRecord(evJoin, side);

    // join, then gather + output projection
    cudaStreamWaitEvent(0, evJoin, 0);
    gather_kernel<<<(M_ * D_ / 4) / 256, 256>>>(Vp, w, delays, Prew);
    gemm_f16_kernel<<<gemm_grid, 256, GEMM_SMEM>>>(Prew, Bow, bo, out);
}

// round 15
// speedup vs baseline: 1.9875x; 1.0059x over previous
#include <cuda_runtime.h>
#include <cuda_bf16.h>
#include <cuda_fp16.h>
#include <math.h>
#include <stdint.h>

#define B_   4
#define L_   4096
#define D_   1024
#define H_   16
#define DK_  64
#define BH_  (B_ * H_)
#define TOPK 8
#define M_   (B_ * L_)   // 16384
#define KW_  512         // fp16 k-pair words per row (K=1024)
#define NKT  16          // KW_/32 mainloop iterations

// ---------------- scratch (device globals; no runtime allocation) ----------
__device__ uint32_t g_Vph[M_ * KW_];      // fp16-pair words of V projection
__device__ uint32_t g_Avw[M_ * KW_];      // fp16-pair words of values
__device__ uint32_t g_Prew[M_ * KW_];     // fp16-pair words of gathered pre
__device__ uint32_t g_Bvw[KW_ * D_];      // fp16-pair words of Wv (kk-major, n-permuted)
__device__ uint32_t g_Bow[KW_ * D_];      // same for Wo
__device__ float g_qm[BH_ * L_];
__device__ float g_km[BH_ * L_];
__device__ float g_Wm[2 * H_ * D_];
__device__ float g_w[BH_ * TOPK];
__device__ int   g_delays[BH_ * TOPK];

// ---------------- helpers ----------------------------------------------------
__device__ __forceinline__ uint32_t smem_u32(const void* p) {
    uint32_t a;
    asm("{ .reg .u64 t; cvta.to.shared.u64 t, %1; cvt.u32.u64 %0, t; }"
        : "=r"(a) : "l"(p));
    return a;
}
__device__ __forceinline__ void cp16(uint32_t dst, const void* src) {
    asm volatile("cp.async.cg.shared.global [%0], [%1], 16;"
                 :: "r"(dst), "l"(src));
}
__device__ __forceinline__ uint32_t pack_f16(float x, float y) {
    __half2 h = __floats2half2_rn(x, y);
    return *(uint32_t*)&h;
}
__device__ __forceinline__ void mma_f16(float* d, const uint32_t* a, const uint32_t* b) {
    asm volatile(
        "mma.sync.aligned.m16n8k16.row.col.f32.f16.f16.f32 "
        "{%0,%1,%2,%3}, {%4,%5,%6,%7}, {%8,%9}, {%0,%1,%2,%3};"
        : "+f"(d[0]), "+f"(d[1]), "+f"(d[2]), "+f"(d[3])
        : "r"(a[0]), "r"(a[1]), "r"(a[2]), "r"(a[3]), "r"(b[0]), "r"(b[1]));
}

// ---------------- convA: fp32 [M,1024] -> fp16-pair words [M,512] ------------
__global__ __launch_bounds__(256) void convA_kernel(
    const float4* __restrict__ X, uint32_t* __restrict__ Aw)
{
    int gid = blockIdx.x * 256 + threadIdx.x;
    int m  = gid >> 8;
    int k4 = gid & 255;
    float4 x = X[gid];
    *(uint2*)(Aw + (size_t)m * KW_ + k4 * 2) =
        make_uint2(pack_f16(x.x, x.y), pack_f16(x.z, x.w));
}

// ---------------- wprep: W fp32 [k][n] -> fp16 words [kk][n] (n permuted) ---
__global__ __launch_bounds__(256) void wprep_f16_kernel(
    const float* __restrict__ W, uint32_t* __restrict__ Bw)
{
    int id = blockIdx.x * 256 + threadIdx.x;
    int kk = id >> 10;
    int p  = id & 1023;
    int g = p & ~63, pp = p & 63;
    int n = g + (((pp & 7) << 3) + (pp >> 3));
    int kb = kk * 2;
    float f0 = __ldg(&W[(size_t)kb * 1024 + n]);
    float f1 = __ldg(&W[(size_t)(kb + 1) * 1024 + n]);
    Bw[id] = pack_f16(f0, f1);
}

// ---------------- fp16 mma GEMM: block 128x128, warp 32x64, occ 2 -----------
// OUT_F16=1: C is packed fp16-pair words [M, 512]; else fp32 [M, 1024]
#define A_ST_W 4096
#define STAGE_W 8192
#define STAGE_BYTES (STAGE_W * 4)
#define GEMM_SMEM (3 * STAGE_BYTES)   // 96 KB

template<int OUT_F16>
__global__ __launch_bounds__(256, 2) void gemm_f16_kernel(
    const uint32_t* __restrict__ Aw, const uint32_t* __restrict__ Bw,
    const float* __restrict__ bias, void* __restrict__ Cv)
{
    extern __shared__ uint32_t sm[];
    const uint32_t su = smem_u32(sm);
    const int tid = threadIdx.x;
    const int bn = blockIdx.x;
    const int bm = blockIdx.y;
    const int wid = tid >> 5, lane = tid & 31;
    const int wm = wid >> 1, wn = wid & 1;
    const int qr = lane >> 2, qc = lane & 3;

    const uint32_t* Ab = Aw + (size_t)(bm * 128 + (tid >> 3)) * KW_ + (tid & 7) * 4;
    const uint32_t* Wb = Bw + (size_t)(tid >> 5) * 1024 + bn * 128 + (tid & 31) * 4;

    uint32_t saoff[4], sboff[4];
    #pragma unroll
    for (int p = 0; p < 4; p++) {
        int row = (tid >> 3) + p * 32;
        saoff[p] = (row * 32 + (((tid & 7) ^ (row & 7)) << 2)) * 4;
        int k = (tid >> 5) + p * 8;
        sboff[p] = (A_ST_W + k * 128 + (((tid & 31) << 2) ^ ((k & 3) << 3))) * 4;
    }

    float acc[2][8][4];
    #pragma unroll
    for (int mb = 0; mb < 2; mb++)
        #pragma unroll
        for (int j = 0; j < 8; j++)
            #pragma unroll
            for (int v = 0; v < 4; v++) acc[mb][j][v] = 0.0f;

    auto load_stage = [&](int st, int kt) {
        uint32_t base = su + st * STAGE_BYTES;
        #pragma unroll
        for (int p = 0; p < 4; p++) {
            cp16(base + saoff[p], Ab + kt * 32 + p * 32 * KW_);
            cp16(base + sboff[p], Wb + (size_t)(kt * 32 + p * 8) * 1024);
        }
    };

    load_stage(0, 0);
    asm volatile("cp.async.commit_group;");
    load_stage(1, 1);
    asm volatile("cp.async.commit_group;");

    const int rowa0 = wm * 32 + qr;
    const int colb = (wn * 64 + qr * 8) ^ (qc << 3);

    for (int kt = 0; kt < NKT; kt++) {
        const int st = kt % 3;
        if (kt < NKT - 2) asm volatile("cp.async.wait_group 1;");
        else              asm volatile("cp.async.wait_group 0;");
        __syncthreads();
        if (kt < NKT - 2) {
            load_stage((kt + 2) % 3, kt + 2);
            asm volatile("cp.async.commit_group;");
        }

        const uint32_t* As = sm + st * STAGE_W;
        const uint32_t* Bs = As + A_ST_W;

        #pragma unroll
        for (int s = 0; s < 4; s++) {
            uint32_t afr[2][4];
            #pragma unroll
            for (int mb = 0; mb < 2; mb++) {
                int row = rowa0 + mb * 16;
                int s0 = (((s * 2)     ^ qr) << 2) + qc;
                int s1 = (((s * 2 + 1) ^ qr) << 2) + qc;
                afr[mb][0] = As[row * 32 + s0];
                afr[mb][1] = As[(row + 8) * 32 + s0];
                afr[mb][2] = As[row * 32 + s1];
                afr[mb][3] = As[(row + 8) * 32 + s1];
            }
            const uint4* br0 = (const uint4*)&Bs[(s * 8 + qc) * 128 + colb];
            const uint4* br1 = (const uint4*)&Bs[(s * 8 + qc + 4) * 128 + colb];
            uint4 b00 = br0[0], b01 = br0[1];
            uint4 b10 = br1[0], b11 = br1[1];
            uint32_t bfr[8][2];
            bfr[0][0] = b00.x; bfr[0][1] = b10.x;
            bfr[1][0] = b00.y; bfr[1][1] = b10.y;
            bfr[2][0] = b00.z; bfr[2][1] = b10.z;
            bfr[3][0] = b00.w; bfr[3][1] = b10.w;
            bfr[4][0] = b01.x; bfr[4][1] = b11.x;
            bfr[5][0] = b01.y; bfr[5][1] = b11.y;
            bfr[6][0] = b01.z; bfr[6][1] = b11.z;
            bfr[7][0] = b01.w; bfr[7][1] = b11.w;

            #pragma unroll
            for (int mb = 0; mb < 2; mb++)
                #pragma unroll
                for (int j = 0; j < 8; j++)
                    mma_f16(acc[mb][j], afr[mb], bfr[j]);
        }
    }

    #pragma unroll
    for (int mb = 0; mb < 2; mb++) {
        int row = bm * 128 + wm * 32 + mb * 16 + qr;
        #pragma unroll
        for (int j = 0; j < 8; j++) {
            int col = bn * 128 + wn * 64 + j * 8 + qc * 2;
            float2 bb = *(const float2*)(bias + col);
            if (OUT_F16) {
                uint32_t* C = (uint32_t*)Cv;
                C[(size_t)row * KW_ + (col >> 1)] =
                    pack_f16(acc[mb][j][0] + bb.x, acc[mb][j][1] + bb.y);
                C[(size_t)(row + 8) * KW_ + (col >> 1)] =
                    pack_f16(acc[mb][j][2] + bb.x, acc[mb][j][3] + bb.y);
            } else {
                float* C = (float*)Cv;
                float2 o0 = make_float2(acc[mb][j][0] + bb.x, acc[mb][j][1] + bb.y);
                float2 o1 = make_float2(acc[mb][j][2] + bb.x, acc[mb][j][3] + bb.y);
                *(float2*)(C + (size_t)row * 1024 + col)       = o0;
                *(float2*)(C + (size_t)(row + 8) * 1024 + col) = o1;
            }
        }
    }
}

// ---------------- mean-reduced weights --------------------------------------
__global__ __launch_bounds__(256) void wmean_kernel(
    const float* __restrict__ Wq, const float* __restrict__ Wk,
    float* __restrict__ Wm)
{
    int id = blockIdx.x * 256 + threadIdx.x;
    int t = id >> 14;
    int h = (id >> 10) & 15;
    int d = id & 1023;
    const float* W = t ? Wk : Wq;
    const float4* p = (const float4*)(W + (size_t)d * 1024 + h * 64);
    float s = 0.0f;
    #pragma unroll
    for (int c = 0; c < 16; c++) {
        float4 v = __ldg(&p[c]);
        s += (v.x + v.y) + (v.z + v.w);
    }
    Wm[id] = s * (1.0f / 64.0f);
}

// ---------------- skinny mean-projection (split q/k; 64KB smem, occ>1) ------
__global__ __launch_bounds__(256) void qkmean_kernel(
    const float* __restrict__ queries, const float* __restrict__ keys,
    const float* __restrict__ Wm, float* __restrict__ qm, float* __restrict__ km)
{
    extern __shared__ float swm[];   // 16384 floats = 64KB
    const int tid = threadIdx.x;
    const int ph = blockIdx.y;
    for (int i = tid * 4; i < 16384; i += 1024)
        *(float4*)(swm + i) = *(const float4*)(Wm + ph * 16384 + i);
    __syncthreads();

    const int w = tid >> 5, lane = tid & 31;
    const int m0 = blockIdx.x * 32 + w * 4;

    const float* src = ph ? keys : queries;
    float* dst = ph ? km : qm;
    const float* base = src + (size_t)m0 * 1024 + lane * 4;
    const float* tw_ = swm + lane * 4;

    float acc[4][16];
    #pragma unroll
    for (int r = 0; r < 4; r++)
        #pragma unroll
        for (int h = 0; h < 16; h++) acc[r][h] = 0.0f;

    #pragma unroll
    for (int c = 0; c < 8; c++) {
        float4 x0 = *(const float4*)(base + 0 * 1024 + c * 128);
        float4 x1 = *(const float4*)(base + 1 * 1024 + c * 128);
        float4 x2 = *(const float4*)(base + 2 * 1024 + c * 128);
        float4 x3 = *(const float4*)(base + 3 * 1024 + c * 128);
        #pragma unroll
        for (int h = 0; h < 16; h++) {
            float4 wv = *(const float4*)(tw_ + h * 1024 + c * 128);
            acc[0][h] += x0.x*wv.x + x0.y*wv.y + x0.z*wv.z + x0.w*wv.w;
            acc[1][h] += x1.x*wv.x + x1.y*wv.y + x1.z*wv.z + x1.w*wv.w;
            acc[2][h] += x2.x*wv.x + x2.y*wv.y + x2.z*wv.z + x2.w*wv.w;
            acc[3][h] += x3.x*wv.x + x3.y*wv.y + x3.z*wv.z + x3.w*wv.w;
        }
    }

    #pragma unroll
    for (int r = 0; r < 4; r++) {
        int m = m0 + r;
        int b = m >> 12, l = m & 4095;
        float* out = dst + (((size_t)b * 16) << 12) + l;
        #pragma unroll
        for (int h = 0; h < 16; h++) {
            float v = acc[r][h];
            v += __shfl_xor_sync(0xFFFFFFFFu, v, 16);
            v += __shfl_xor_sync(0xFFFFFFFFu, v, 8);
            v += __shfl_xor_sync(0xFFFFFFFFu, v, 4);
            v += __shfl_xor_sync(0xFFFFFFFFu, v, 2);
            v += __shfl_xor_sync(0xFFFFFFFFu, v, 1);
            if (lane == h) out[(size_t)h << 12] = v;
        }
    }
}

// ---------------- FFT correlation + top-8 + softmax (fused, 512 thr) --------
__global__ __launch_bounds__(512) void fft_corr_top8_kernel(
    const float* __restrict__ qm, const float* __restrict__ km,
    float* __restrict__ w, int* __restrict__ delays)
{
    extern __shared__ float2 fsm[];
    float2* buf0 = fsm;
    float2* buf1 = fsm + 4096;
    float2* tw   = fsm + 8192;
    float*  sc   = (float*)(fsm + 8192);
    __shared__ float svals[512];
    __shared__ int   sidx[512];
    __shared__ float topv[TOPK];
    __shared__ int   topi[TOPK];

    const int bh = blockIdx.x, tid = threadIdx.x;
    const float* q = qm + (size_t)bh * L_;
    const float* k = km + (size_t)bh * L_;
    for (int i = tid; i < 4096; i += 512) buf0[i] = make_float2(q[i], k[i]);
    for (int r = tid; r < 2048; r += 512) {
        float sv, cv;
        __sincosf(-6.2831853071795865f * (float)r / 4096.0f, &sv, &cv);
        tw[r] = make_float2(cv, sv);
    }
    __syncthreads();

    // FFT #1
    {
        float2 *x = buf0, *y = buf1;
        for (int t = 0; t < 12; t++) {
            int s = 1 << t;
            #pragma unroll
            for (int ii = 0; ii < 4; ii++) {
                int idx = tid + ii * 512;
                float2 a = x[idx];
                float2 b = x[idx + 2048];
                int r = idx & ~(s - 1);
                int kl = idx & (s - 1);
                float2 wv = tw[r];
                float dx = a.x - b.x, dy = a.y - b.y;
                y[2 * r + kl]     = make_float2(a.x + b.x, a.y + b.y);
                y[2 * r + kl + s] = make_float2(dx * wv.x - dy * wv.y,
                                                dx * wv.y + dy * wv.x);
            }
            __syncthreads();
            float2* t2 = x; x = y; y = t2;
        }
    }

    // Hermitian split + conj(Q*conj(K)) into buf1
    for (int i = tid; i < 4096; i += 512) {
        float2 zi = buf0[i];
        float2 zn = buf0[(4096 - i) & 4095];
        float qx = 0.5f * (zi.x + zn.x);
        float qy = 0.5f * (zi.y - zn.y);
        float ux = zi.x - zn.x;
        float uy = zi.y + zn.y;
        float kx = 0.5f * uy;
        float ky = -0.5f * ux;
        float px = qx * kx + qy * ky;
        float py = qy * kx - qx * ky;
        buf1[i] = make_float2(px, -py);
    }
    __syncthreads();

    // FFT #2
    {
        float2 *x = buf1, *y = buf0;
        for (int t = 0; t < 12; t++) {
            int s = 1 << t;
            #pragma unroll
            for (int ii = 0; ii < 4; ii++) {
                int idx = tid + ii * 512;
                float2 a = x[idx];
                float2 b = x[idx + 2048];
                int r = idx & ~(s - 1);
                int kl = idx & (s - 1);
                float2 wv = tw[r];
                float dx = a.x - b.x, dy = a.y - b.y;
                y[2 * r + kl]     = make_float2(a.x + b.x, a.y + b.y);
                y[2 * r + kl + s] = make_float2(dx * wv.x - dy * wv.y,
                                                dx * wv.y + dy * wv.x);
            }
            __syncthreads();
            float2* t2 = x; x = y; y = t2;
        }
    }

    for (int i = tid; i < 4096; i += 512)
        sc[i] = buf1[i].x * (1.0f / 4096.0f);
    __syncthreads();

    for (int r = 0; r < TOPK; r++) {
        float best = -INFINITY; int bi = 0;
        for (int i = tid; i < 4096; i += 512) {
            float v = sc[i];
            if (v > best) { best = v; bi = i; }
        }
        svals[tid] = best;
        sidx[tid] = bi;
        __syncthreads();
        for (int s = 256; s > 0; s >>= 1) {
            if (tid < s) {
                float v2 = svals[tid + s];
                int   i2 = sidx[tid + s];
                float v1 = svals[tid];
                int   i1 = sidx[tid];
                if (v2 > v1 || (v2 == v1 && i2 < i1)) {
                    svals[tid] = v2;
                    sidx[tid] = i2;
                }
            }
            __syncthreads();
        }
        if (tid == 0) {
            topv[r] = svals[0];
            topi[r] = sidx[0];
            sc[sidx[0]] = -INFINITY;
        }
        __syncthreads();
    }

    if (tid == 0) {
        float mx = topv[0];
        float e[TOPK], s = 0.0f;
        #pragma unroll
        for (int r = 0; r < TOPK; r++) { e[r] = expf(topv[r] - mx); s += e[r]; }
        float inv = 1.0f / s;
        #pragma unroll
        for (int r = 0; r < TOPK; r++) {
            w[bh * TOPK + r] = e[r] * inv;
            delays[bh * TOPK + r] = topi[r];
        }
    }
}

// ---------------- gather: fp16 V words -> weighted roll -> fp16 words --------
__global__ __launch_bounds__(256) void gather_kernel(
    const uint32_t* __restrict__ Vph, const float* __restrict__ w,
    const int* __restrict__ delays, uint32_t* __restrict__ Prew)
{
    unsigned gid = blockIdx.x * blockDim.x + threadIdx.x;   // 4 channels each
    int d4 = gid & 255;
    int l  = (gid >> 8) & (L_ - 1);
    int b  = gid >> 20;
    int h  = d4 >> 4;
    int bh = b * H_ + h;

    float4 a = make_float4(0.f, 0.f, 0.f, 0.f);
    #pragma unroll
    for (int r = 0; r < TOPK; r++) {
        float wr = __ldg(&w[bh * TOPK + r]);
        int   dl = __ldg(&delays[bh * TOPK + r]);
        int   lm = (l - dl) & (L_ - 1);
        uint2 vv = *(const uint2*)(Vph + (size_t)(b * L_ + lm) * KW_ + d4 * 2);
        __half2 v0 = *(__half2*)&vv.x;
        __half2 v1 = *(__half2*)&vv.y;
        float2 f0 = __half22float2(v0);
        float2 f1 = __half22float2(v1);
        a.x += wr * f0.x; a.y += wr * f0.y;
        a.z += wr * f1.x; a.w += wr * f1.y;
    }
    int m = b * L_ + l;
    *(uint2*)(Prew + (size_t)m * KW_ + d4 * 2) =
        make_uint2(pack_f16(a.x, a.y), pack_f16(a.z, a.w));
}

// ---------------- launch ------------------------------------------------------
extern "C" void kernel_launch(void* const* d_in, const int* in_sizes, int n_in,
                              void* d_out, int out_size)
{
    const float* queries = (const float*)d_in[0];
    const float* keys    = (const float*)d_in[1];
    const float* values  = (const float*)d_in[2];
    const float* Wq = (const float*)d_in[3];
    const float* Wk = (const float*)d_in[5];
    const float* Wv = (const float*)d_in[7];
    const float* bv = (const float*)d_in[8];
    const float* Wo = (const float*)d_in[9];
    const float* bo = (const float*)d_in[10];
    float* out = (float*)d_out;

    float *qm, *km, *Wm, *w;
    uint32_t *Vph, *Avw, *Prew, *Bvw, *Bow;
    int* delays;
    cudaGetSymbolAddress((void**)&Vph, g_Vph);
    cudaGetSymbolAddress((void**)&Avw, g_Avw);
    cudaGetSymbolAddress((void**)&Prew, g_Prew);
    cudaGetSymbolAddress((void**)&Bvw, g_Bvw);
    cudaGetSymbolAddress((void**)&Bow, g_Bow);
    cudaGetSymbolAddress((void**)&qm, g_qm);
    cudaGetSymbolAddress((void**)&km, g_km);
    cudaGetSymbolAddress((void**)&Wm, g_Wm);
    cudaGetSymbolAddress((void**)&w, g_w);
    cudaGetSymbolAddress((void**)&delays, g_delays);

    cudaFuncSetAttribute(gemm_f16_kernel<0>,
                         cudaFuncAttributeMaxDynamicSharedMemorySize, GEMM_SMEM);
    cudaFuncSetAttribute(gemm_f16_kernel<1>,
                         cudaFuncAttributeMaxDynamicSharedMemorySize, GEMM_SMEM);
    cudaFuncSetAttribute(qkmean_kernel,
                         cudaFuncAttributeMaxDynamicSharedMemorySize, 65536);
    cudaFuncSetAttribute(fft_corr_top8_kernel,
                         cudaFuncAttributeMaxDynamicSharedMemorySize, 81920);

    dim3 gemm_grid(8, 128);

    // fork-join: side chain depends only on inputs
    cudaStream_t side;
    cudaEvent_t evFork, evJoin;
    cudaStreamCreateWithFlags(&side, cudaStreamNonBlocking);
    cudaEventCreateWithFlags(&evFork, cudaEventDisableTiming);
    cudaEventCreateWithFlags(&evJoin, cudaEventDisableTiming);

    cudaEventRecord(evFork, 0);
    cudaStreamWaitEvent(side, evFork, 0);

    // main stream: V projection (critical path), fp16 output
    wprep_f16_kernel<<<2048, 256>>>(Wv, Bvw);
    convA_kernel<<<M_, 256>>>((const float4*)values, Avw);
    gemm_f16_kernel<1><<<gemm_grid, 256, GEMM_SMEM>>>(Avw, Bvw, bv, Vph);

    // side stream: mean path + Wo prep
    wprep_f16_kernel<<<2048, 256, 0, side>>>(Wo, Bow);
    wmean_kernel<<<128, 256, 0, side>>>(Wq, Wk, Wm);
    {
        dim3 qk_grid(512, 2);
        qkmean_kernel<<<qk_grid, 256, 65536, side>>>(queries, keys, Wm, qm, km);
    }
    fft_corr_top8_kernel<<<BH_, 512, 81920, side>>>(qm, km, w, delays);
    cudaEventRecord(evJoin, side);

    // join, then gather + output projection (fp32 output)
    cudaStreamWaitEvent(0, evJoin, 0);
    gather_kernel<<<(M_ * D_ / 4) / 256, 256>>>(Vph, w, delays, Prew);
    gemm_f16_kernel<0><<<gemm_grid, 256, GEMM_SMEM>>>(Prew, Bow, bo, out);
}

// round 17
// speedup vs baseline: 2.0826x; 1.0479x over previous
#include <cuda_runtime.h>
#include <cuda_bf16.h>
#include <cuda_fp16.h>
#include <math.h>
#include <stdint.h>

#define B_   4
#define L_   4096
#define D_   1024
#define H_   16
#define DK_  64
#define BH_  (B_ * H_)
#define TOPK 8
#define M_   (B_ * L_)   // 16384
#define KW_  512         // fp16 k-pair words per row (K=1024)
#define NKT  16          // KW_/32 mainloop iterations

// ---------------- scratch (device globals; no runtime allocation) ----------
__device__ uint32_t g_Vph[M_ * KW_];      // fp16-pair words of V projection
__device__ uint32_t g_Avw[M_ * KW_];      // fp16-pair words of values
__device__ uint32_t g_Prew[M_ * KW_];     // fp16-pair words of gathered pre
__device__ uint32_t g_Bvw[KW_ * D_];      // fp16-pair words of Wv (kk-major, n-permuted)
__device__ uint32_t g_Bow[KW_ * D_];      // same for Wo
__device__ float g_qm[BH_ * L_];
__device__ float g_km[BH_ * L_];
__device__ float g_Wm[2 * H_ * D_];
__device__ float g_w[BH_ * TOPK];
__device__ int   g_delays[BH_ * TOPK];

// ---------------- helpers ----------------------------------------------------
__device__ __forceinline__ uint32_t smem_u32(const void* p) {
    uint32_t a;
    asm("{ .reg .u64 t; cvta.to.shared.u64 t, %1; cvt.u32.u64 %0, t; }"
        : "=r"(a) : "l"(p));
    return a;
}
__device__ __forceinline__ void cp16(uint32_t dst, const void* src) {
    asm volatile("cp.async.cg.shared.global [%0], [%1], 16;"
                 :: "r"(dst), "l"(src));
}
__device__ __forceinline__ uint32_t pack_f16(float x, float y) {
    __half2 h = __floats2half2_rn(x, y);
    return *(uint32_t*)&h;
}
__device__ __forceinline__ void mma_f16(float* d, const uint32_t* a, const uint32_t* b) {
    asm volatile(
        "mma.sync.aligned.m16n8k16.row.col.f32.f16.f16.f32 "
        "{%0,%1,%2,%3}, {%4,%5,%6,%7}, {%8,%9}, {%0,%1,%2,%3};"
        : "+f"(d[0]), "+f"(d[1]), "+f"(d[2]), "+f"(d[3])
        : "r"(a[0]), "r"(a[1]), "r"(a[2]), "r"(a[3]), "r"(b[0]), "r"(b[1]));
}

// ---------------- convA: fp32 [M,1024] -> fp16-pair words [M,512] ------------
__global__ __launch_bounds__(256) void convA_kernel(
    const float4* __restrict__ X, uint32_t* __restrict__ Aw)
{
    int gid = blockIdx.x * 256 + threadIdx.x;
    int m  = gid >> 8;
    int k4 = gid & 255;
    float4 x = X[gid];
    *(uint2*)(Aw + (size_t)m * KW_ + k4 * 2) =
        make_uint2(pack_f16(x.x, x.y), pack_f16(x.z, x.w));
}

// ---------------- wprep: BOTH weights in one launch --------------------------
// grid 4096: first 2048 blocks -> (Wa -> Ba), rest -> (Wb -> Bb)
__global__ __launch_bounds__(256) void wprep_f16_kernel(
    const float* __restrict__ Wa, uint32_t* __restrict__ Ba,
    const float* __restrict__ Wb, uint32_t* __restrict__ Bb)
{
    int blk = blockIdx.x;
    const float* W = (blk < 2048) ? Wa : Wb;
    uint32_t* Bw = (blk < 2048) ? Ba : Bb;
    int id = (blk & 2047) * 256 + threadIdx.x;
    int kk = id >> 10;
    int p  = id & 1023;
    int g = p & ~63, pp = p & 63;
    int n = g + (((pp & 7) << 3) + (pp >> 3));
    int kb = kk * 2;
    float f0 = __ldg(&W[(size_t)kb * 1024 + n]);
    float f1 = __ldg(&W[(size_t)(kb + 1) * 1024 + n]);
    Bw[id] = pack_f16(f0, f1);
}

// ---------------- fp16 mma GEMM: block 128x128, warp 32x64, occ 2 -----------
// OUT_F16=1: C is packed fp16-pair words [M, 512]; else fp32 [M, 1024]
#define A_ST_W 4096
#define STAGE_W 8192
#define STAGE_BYTES (STAGE_W * 4)
#define GEMM_SMEM (3 * STAGE_BYTES)   // 96 KB

template<int OUT_F16>
__global__ __launch_bounds__(256, 2) void gemm_f16_kernel(
    const uint32_t* __restrict__ Aw, const uint32_t* __restrict__ Bw,
    const float* __restrict__ bias, void* __restrict__ Cv)
{
    extern __shared__ uint32_t sm[];
    const uint32_t su = smem_u32(sm);
    const int tid = threadIdx.x;
    const int bn = blockIdx.x;
    const int bm = blockIdx.y;
    const int wid = tid >> 5, lane = tid & 31;
    const int wm = wid >> 1, wn = wid & 1;
    const int qr = lane >> 2, qc = lane & 3;

    const uint32_t* Ab = Aw + (size_t)(bm * 128 + (tid >> 3)) * KW_ + (tid & 7) * 4;
    const uint32_t* Wb = Bw + (size_t)(tid >> 5) * 1024 + bn * 128 + (tid & 31) * 4;

    uint32_t saoff[4], sboff[4];
    #pragma unroll
    for (int p = 0; p < 4; p++) {
        int row = (tid >> 3) + p * 32;
        saoff[p] = (row * 32 + (((tid & 7) ^ (row & 7)) << 2)) * 4;
        int k = (tid >> 5) + p * 8;
        sboff[p] = (A_ST_W + k * 128 + (((tid & 31) << 2) ^ ((k & 3) << 3))) * 4;
    }

    float acc[2][8][4];
    #pragma unroll
    for (int mb = 0; mb < 2; mb++)
        #pragma unroll
        for (int j = 0; j < 8; j++)
            #pragma unroll
            for (int v = 0; v < 4; v++) acc[mb][j][v] = 0.0f;

    auto load_stage = [&](int st, int kt) {
        uint32_t base = su + st * STAGE_BYTES;
        #pragma unroll
        for (int p = 0; p < 4; p++) {
            cp16(base + saoff[p], Ab + kt * 32 + p * 32 * KW_);
            cp16(base + sboff[p], Wb + (size_t)(kt * 32 + p * 8) * 1024);
        }
    };

    load_stage(0, 0);
    asm volatile("cp.async.commit_group;");
    load_stage(1, 1);
    asm volatile("cp.async.commit_group;");

    const int rowa0 = wm * 32 + qr;
    const int colb = (wn * 64 + qr * 8) ^ (qc << 3);

    for (int kt = 0; kt < NKT; kt++) {
        const int st = kt % 3;
        if (kt < NKT - 2) asm volatile("cp.async.wait_group 1;");
        else              asm volatile("cp.async.wait_group 0;");
        __syncthreads();
        if (kt < NKT - 2) {
            load_stage((kt + 2) % 3, kt + 2);
            asm volatile("cp.async.commit_group;");
        }

        const uint32_t* As = sm + st * STAGE_W;
        const uint32_t* Bs = As + A_ST_W;

        #pragma unroll
        for (int s = 0; s < 4; s++) {
            uint32_t afr[2][4];
            #pragma unroll
            for (int mb = 0; mb < 2; mb++) {
                int row = rowa0 + mb * 16;
                int s0 = (((s * 2)     ^ qr) << 2) + qc;
                int s1 = (((s * 2 + 1) ^ qr) << 2) + qc;
                afr[mb][0] = As[row * 32 + s0];
                afr[mb][1] = As[(row + 8) * 32 + s0];
                afr[mb][2] = As[row * 32 + s1];
                afr[mb][3] = As[(row + 8) * 32 + s1];
            }
            const uint4* br0 = (const uint4*)&Bs[(s * 8 + qc) * 128 + colb];
            const uint4* br1 = (const uint4*)&Bs[(s * 8 + qc + 4) * 128 + colb];
            uint4 b00 = br0[0], b01 = br0[1];
            uint4 b10 = br1[0], b11 = br1[1];
            uint32_t bfr[8][2];
            bfr[0][0] = b00.x; bfr[0][1] = b10.x;
            bfr[1][0] = b00.y; bfr[1][1] = b10.y;
            bfr[2][0] = b00.z; bfr[2][1] = b10.z;
            bfr[3][0] = b00.w; bfr[3][1] = b10.w;
            bfr[4][0] = b01.x; bfr[4][1] = b11.x;
            bfr[5][0] = b01.y; bfr[5][1] = b11.y;
            bfr[6][0] = b01.z; bfr[6][1] = b11.z;
            bfr[7][0] = b01.w; bfr[7][1] = b11.w;

            #pragma unroll
            for (int mb = 0; mb < 2; mb++)
                #pragma unroll
                for (int j = 0; j < 8; j++)
                    mma_f16(acc[mb][j], afr[mb], bfr[j]);
        }
    }

    #pragma unroll
    for (int mb = 0; mb < 2; mb++) {
        int row = bm * 128 + wm * 32 + mb * 16 + qr;
        #pragma unroll
        for (int j = 0; j < 8; j++) {
            int col = bn * 128 + wn * 64 + j * 8 + qc * 2;
            float2 bb = *(const float2*)(bias + col);
            if (OUT_F16) {
                uint32_t* C = (uint32_t*)Cv;
                C[(size_t)row * KW_ + (col >> 1)] =
                    pack_f16(acc[mb][j][0] + bb.x, acc[mb][j][1] + bb.y);
                C[(size_t)(row + 8) * KW_ + (col >> 1)] =
                    pack_f16(acc[mb][j][2] + bb.x, acc[mb][j][3] + bb.y);
            } else {
                float* C = (float*)Cv;
                float2 o0 = make_float2(acc[mb][j][0] + bb.x, acc[mb][j][1] + bb.y);
                float2 o1 = make_float2(acc[mb][j][2] + bb.x, acc[mb][j][3] + bb.y);
                *(float2*)(C + (size_t)row * 1024 + col)       = o0;
                *(float2*)(C + (size_t)(row + 8) * 1024 + col) = o1;
            }
        }
    }
}

// ---------------- mean-reduced weights --------------------------------------
__global__ __launch_bounds__(256) void wmean_kernel(
    const float* __restrict__ Wq, const float* __restrict__ Wk,
    float* __restrict__ Wm)
{
    int id = blockIdx.x * 256 + threadIdx.x;
    int t = id >> 14;
    int h = (id >> 10) & 15;
    int d = id & 1023;
    const float* W = t ? Wk : Wq;
    const float4* p = (const float4*)(W + (size_t)d * 1024 + h * 64);
    float s = 0.0f;
    #pragma unroll
    for (int c = 0; c < 16; c++) {
        float4 v = __ldg(&p[c]);
        s += (v.x + v.y) + (v.z + v.w);
    }
    Wm[id] = s * (1.0f / 64.0f);
}

// ---------------- skinny mean-projection (split q/k; 64KB smem) -------------
__global__ __launch_bounds__(256) void qkmean_kernel(
    const float* __restrict__ queries, const float* __restrict__ keys,
    const float* __restrict__ Wm, float* __restrict__ qm, float* __restrict__ km)
{
    extern __shared__ float swm[];   // 16384 floats = 64KB
    const int tid = threadIdx.x;
    const int ph = blockIdx.y;
    for (int i = tid * 4; i < 16384; i += 1024)
        *(float4*)(swm + i) = *(const float4*)(Wm + ph * 16384 + i);
    __syncthreads();

    const int w = tid >> 5, lane = tid & 31;
    const int m0 = blockIdx.x * 32 + w * 4;

    const float* src = ph ? keys : queries;
    float* dst = ph ? km : qm;
    const float* base = src + (size_t)m0 * 1024 + lane * 4;
    const float* tw_ = swm + lane * 4;

    float acc[4][16];
    #pragma unroll
    for (int r = 0; r < 4; r++)
        #pragma unroll
        for (int h = 0; h < 16; h++) acc[r][h] = 0.0f;

    #pragma unroll
    for (int c = 0; c < 8; c++) {
        float4 x0 = *(const float4*)(base + 0 * 1024 + c * 128);
        float4 x1 = *(const float4*)(base + 1 * 1024 + c * 128);
        float4 x2 = *(const float4*)(base + 2 * 1024 + c * 128);
        float4 x3 = *(const float4*)(base + 3 * 1024 + c * 128);
        #pragma unroll
        for (int h = 0; h < 16; h++) {
            float4 wv = *(const float4*)(tw_ + h * 1024 + c * 128);
            acc[0][h] += x0.x*wv.x + x0.y*wv.y + x0.z*wv.z + x0.w*wv.w;
            acc[1][h] += x1.x*wv.x + x1.y*wv.y + x1.z*wv.z + x1.w*wv.w;
            acc[2][h] += x2.x*wv.x + x2.y*wv.y + x2.z*wv.z + x2.w*wv.w;
            acc[3][h] += x3.x*wv.x + x3.y*wv.y + x3.z*wv.z + x3.w*wv.w;
        }
    }

    #pragma unroll
    for (int r = 0; r < 4; r++) {
        int m = m0 + r;
        int b = m >> 12, l = m & 4095;
        float* out = dst + (((size_t)b * 16) << 12) + l;
        #pragma unroll
        for (int h = 0; h < 16; h++) {
            float v = acc[r][h];
            v += __shfl_xor_sync(0xFFFFFFFFu, v, 16);
            v += __shfl_xor_sync(0xFFFFFFFFu, v, 8);
            v += __shfl_xor_sync(0xFFFFFFFFu, v, 4);
            v += __shfl_xor_sync(0xFFFFFFFFu, v, 2);
            v += __shfl_xor_sync(0xFFFFFFFFu, v, 1);
            if (lane == h) out[(size_t)h << 12] = v;
        }
    }
}

// ---------------- FFT correlation + top-8 + softmax (fused, 1024 thr) -------
__global__ __launch_bounds__(1024) void fft_corr_top8_kernel(
    const float* __restrict__ qm, const float* __restrict__ km,
    float* __restrict__ w, int* __restrict__ delays)
{
    extern __shared__ float2 fsm[];
    float2* buf0 = fsm;
    float2* buf1 = fsm + 4096;
    float2* tw   = fsm + 8192;
    float*  sc   = (float*)(fsm + 8192);
    __shared__ float svals[1024];
    __shared__ int   sidx[1024];
    __shared__ float topv[TOPK];
    __shared__ int   topi[TOPK];

    const int bh = blockIdx.x, tid = threadIdx.x;
    const float* q = qm + (size_t)bh * L_;
    const float* k = km + (size_t)bh * L_;
    for (int i = tid; i < 4096; i += 1024) buf0[i] = make_float2(q[i], k[i]);
    for (int r = tid; r < 2048; r += 1024) {
        float sv, cv;
        __sincosf(-6.2831853071795865f * (float)r / 4096.0f, &sv, &cv);
        tw[r] = make_float2(cv, sv);
    }
    __syncthreads();

    // FFT #1
    {
        float2 *x = buf0, *y = buf1;
        for (int t = 0; t < 12; t++) {
            int s = 1 << t;
            #pragma unroll
            for (int ii = 0; ii < 2; ii++) {
                int idx = tid + ii * 1024;
                float2 a = x[idx];
                float2 b = x[idx + 2048];
                int r = idx & ~(s - 1);
                int kl = idx & (s - 1);
                float2 wv = tw[r];
                float dx = a.x - b.x, dy = a.y - b.y;
                y[2 * r + kl]     = make_float2(a.x + b.x, a.y + b.y);
                y[2 * r + kl + s] = make_float2(dx * wv.x - dy * wv.y,
                                                dx * wv.y + dy * wv.x);
            }
            __syncthreads();
            float2* t2 = x; x = y; y = t2;
        }
    }

    // Hermitian split + conj(Q*conj(K)) into buf1
    for (int i = tid; i < 4096; i += 1024) {
        float2 zi = buf0[i];
        float2 zn = buf0[(4096 - i) & 4095];
        float qx = 0.5f * (zi.x + zn.x);
        float qy = 0.5f * (zi.y - zn.y);
        float ux = zi.x - zn.x;
        float uy = zi.y + zn.y;
        float kx = 0.5f * uy;
        float ky = -0.5f * ux;
        float px = qx * kx + qy * ky;
        float py = qy * kx - qx * ky;
        buf1[i] = make_float2(px, -py);
    }
    __syncthreads();

    // FFT #2
    {
        float2 *x = buf1, *y = buf0;
        for (int t = 0; t < 12; t++) {
            int s = 1 << t;
            #pragma unroll
            for (int ii = 0; ii < 2; ii++) {
                int idx = tid + ii * 1024;
                float2 a = x[idx];
                float2 b = x[idx + 2048];
                int r = idx & ~(s - 1);
                int kl = idx & (s - 1);
                float2 wv = tw[r];
                float dx = a.x - b.x, dy = a.y - b.y;
                y[2 * r + kl]     = make_float2(a.x + b.x, a.y + b.y);
                y[2 * r + kl + s] = make_float2(dx * wv.x - dy * wv.y,
                                                dx * wv.y + dy * wv.x);
            }
            __syncthreads();
            float2* t2 = x; x = y; y = t2;
        }
    }

    for (int i = tid; i < 4096; i += 1024)
        sc[i] = buf1[i].x * (1.0f / 4096.0f);
    __syncthreads();

    for (int r = 0; r < TOPK; r++) {
        float best = -INFINITY; int bi = 0;
        for (int i = tid; i < 4096; i += 1024) {
            float v = sc[i];
            if (v > best) { best = v; bi = i; }
        }
        svals[tid] = best;
        sidx[tid] = bi;
        __syncthreads();
        for (int s = 512; s > 0; s >>= 1) {
            if (tid < s) {
                float v2 = svals[tid + s];
                int   i2 = sidx[tid + s];
                float v1 = svals[tid];
                int   i1 = sidx[tid];
                if (v2 > v1 || (v2 == v1 && i2 < i1)) {
                    svals[tid] = v2;
                    sidx[tid] = i2;
                }
            }
            __syncthreads();
        }
        if (tid == 0) {
            topv[r] = svals[0];
            topi[r] = sidx[0];
            sc[sidx[0]] = -INFINITY;
        }
        __syncthreads();
    }

    if (tid == 0) {
        float mx = topv[0];
        float e[TOPK], s = 0.0f;
        #pragma unroll
        for (int r = 0; r < TOPK; r++) { e[r] = expf(topv[r] - mx); s += e[r]; }
        float inv = 1.0f / s;
        #pragma unroll
        for (int r = 0; r < TOPK; r++) {
            w[bh * TOPK + r] = e[r] * inv;
            delays[bh * TOPK + r] = topi[r];
        }
    }
}

// ---------------- gather: fp16 V words -> weighted roll -> fp16 words --------
__global__ __launch_bounds__(256) void gather_kernel(
    const uint32_t* __restrict__ Vph, const float* __restrict__ w,
    const int* __restrict__ delays, uint32_t* __restrict__ Prew)
{
    unsigned gid = blockIdx.x * blockDim.x + threadIdx.x;   // 4 channels each
    int d4 = gid & 255;
    int l  = (gid >> 8) & (L_ - 1);
    int b  = gid >> 20;
    int h  = d4 >> 4;
    int bh = b * H_ + h;

    float4 a = make_float4(0.f, 0.f, 0.f, 0.f);
    #pragma unroll
    for (int r = 0; r < TOPK; r++) {
        float wr = __ldg(&w[bh * TOPK + r]);
        int   dl = __ldg(&delays[bh * TOPK + r]);
        int   lm = (l - dl) & (L_ - 1);
        uint2 vv = *(const uint2*)(Vph + (size_t)(b * L_ + lm) * KW_ + d4 * 2);
        __half2 v0 = *(__half2*)&vv.x;
        __half2 v1 = *(__half2*)&vv.y;
        float2 f0 = __half22float2(v0);
        float2 f1 = __half22float2(v1);
        a.x += wr * f0.x; a.y += wr * f0.y;
        a.z += wr * f1.x; a.w += wr * f1.y;
    }
    int m = b * L_ + l;
    *(uint2*)(Prew + (size_t)m * KW_ + d4 * 2) =
        make_uint2(pack_f16(a.x, a.y), pack_f16(a.z, a.w));
}

// ---------------- launch ------------------------------------------------------
extern "C" void kernel_launch(void* const* d_in, const int* in_sizes, int n_in,
                              void* d_out, int out_size)
{
    const float* queries = (const float*)d_in[0];
    const float* keys    = (const float*)d_in[1];
    const float* values  = (const float*)d_in[2];
    const float* Wq = (const float*)d_in[3];
    const float* Wk = (const float*)d_in[5];
    const float* Wv = (const float*)d_in[7];
    const float* bv = (const float*)d_in[8];
    const float* Wo = (const float*)d_in[9];
    const float* bo = (const float*)d_in[10];
    float* out = (float*)d_out;

    float *qm, *km, *Wm, *w;
    uint32_t *Vph, *Avw, *Prew, *Bvw, *Bow;
    int* delays;
    cudaGetSymbolAddress((void**)&Vph, g_Vph);
    cudaGetSymbolAddress((void**)&Avw, g_Avw);
    cudaGetSymbolAddress((void**)&Prew, g_Prew);
    cudaGetSymbolAddress((void**)&Bvw, g_Bvw);
    cudaGetSymbolAddress((void**)&Bow, g_Bow);
    cudaGetSymbolAddress((void**)&qm, g_qm);
    cudaGetSymbolAddress((void**)&km, g_km);
    cudaGetSymbolAddress((void**)&Wm, g_Wm);
    cudaGetSymbolAddress((void**)&w, g_w);
    cudaGetSymbolAddress((void**)&delays, g_delays);

    cudaFuncSetAttribute(gemm_f16_kernel<0>,
                         cudaFuncAttributeMaxDynamicSharedMemorySize, GEMM_SMEM);
    cudaFuncSetAttribute(gemm_f16_kernel<1>,
                         cudaFuncAttributeMaxDynamicSharedMemorySize, GEMM_SMEM);
    cudaFuncSetAttribute(qkmean_kernel,
                         cudaFuncAttributeMaxDynamicSharedMemorySize, 65536);
    cudaFuncSetAttribute(fft_corr_top8_kernel,
                         cudaFuncAttributeMaxDynamicSharedMemorySize, 81920);

    dim3 gemm_grid(8, 128);

    // fork-join: side chain depends only on inputs (R14 topology — small graph)
    cudaStream_t side;
    cudaEvent_t evFork, evJoin;
    cudaStreamCreateWithFlags(&side, cudaStreamNonBlocking);
    cudaEventCreateWithFlags(&evFork, cudaEventDisableTiming);
    cudaEventCreateWithFlags(&evJoin, cudaEventDisableTiming);

    cudaEventRecord(evFork, 0);
    cudaStreamWaitEvent(side, evFork, 0);

    // main stream: weight prep (both) + V projection (critical path)
    wprep_f16_kernel<<<4096, 256>>>(Wv, Bvw, Wo, Bow);
    convA_kernel<<<M_, 256>>>((const float4*)values, Avw);
    gemm_f16_kernel<1><<<gemm_grid, 256, GEMM_SMEM>>>(Avw, Bvw, bv, Vph);

    // side stream: mean path
    wmean_kernel<<<128, 256, 0, side>>>(Wq, Wk, Wm);
    {
        dim3 qk_grid(512, 2);
        qkmean_kernel<<<qk_grid, 256, 65536, side>>>(queries, keys, Wm, qm, km);
    }
    fft_corr_top8_kernel<<<BH_, 1024, 81920, side>>>(qm, km, w, delays);
    cudaEventRecord(evJoin, side);

    // join, then gather + output projection (fp32 output)
    cudaStreamWaitEvent(0, evJoin, 0);
    gather_kernel<<<(M_ * D_ / 4) / 256, 256>>>(Vph, w, delays, Prew);
    gemm_f16_kernel<0><<<gemm_grid, 256, GEMM_SMEM>>>(Prew, Bow, bo, out);
}